// round 15
// baseline (speedup 1.0000x reference)
#include <cuda_runtime.h>
#include <cuda_fp16.h>
#include <float.h>
#include <stdint.h>

#define N_ROWS   131072
#define DIM      128
#define K_CODES  4096
#define DECAY    0.99f
#define ONE_M_D  0.01f
#define EPS      1e-5f
#define MARGIN   0.12f
#define MARGIN2  2e-3f
#define FIX_CAP  32768
#define FIX2_CAP 8192

// Output layout (tuple order, flattened, f32)
#define OFF_Q      0
#define OFF_LOSS   16777216
#define OFF_NSMALL 16777217
#define OFF_IND    16777218
#define OFF_ENEW   16908290
#define OFF_CS     17432578
#define OFF_EAVG   17436674

// ---------------- device scratch (no allocation) ----------------
__device__ __align__(16) float  g_embedT[K_CODES * DIM];
__device__ __align__(16) __half g_ehi[K_CODES * DIM];
__device__ __align__(16) __half g_elo[K_CODES * DIM];
__device__ __align__(16) float  g_enorm[K_CODES];
__device__ double g_losspart[128];
__device__ float  g_n;
__device__ int    g_fixn;
__device__ int    g_fixlist[FIX_CAP];
__device__ int    g_fixn2;
__device__ int    g_fixlist2[FIX2_CAP];
__device__ float  g_qv1[FIX_CAP * 4];
__device__ float  g_qv2[FIX_CAP * 4];
__device__ int    g_qi1[FIX_CAP * 4];
__device__ float  g_pv[(FIX2_CAP + 16) * 8];
__device__ int    g_pi[(FIX2_CAP + 16) * 8];
__device__ int    g_hist[K_CODES];
__device__ int    g_off[K_CODES];
__device__ int    g_cur[K_CODES];
__device__ int    g_rowlist[N_ROWS];

// ---------------- helpers ----------------
#define CP_ASYNC16(dst, src) \
    asm volatile("cp.async.cg.shared.global [%0], [%1], 16;" :: "r"(dst), "l"(src) : "memory")
#define CP_COMMIT() asm volatile("cp.async.commit_group;" ::: "memory")
#define CP_WAIT(n)  asm volatile("cp.async.wait_group %0;" :: "n"(n) : "memory")

__device__ __forceinline__ uint32_t s2u(const void* p) {
    uint32_t a;
    asm("{ .reg .u64 t; cvta.to.shared.u64 t, %1; cvt.u32.u64 %0, t; }" : "=r"(a) : "l"(p));
    return a;
}

__device__ __forceinline__ void ldsm_x4(uint32_t& r0, uint32_t& r1, uint32_t& r2, uint32_t& r3,
                                        uint32_t addr) {
    asm volatile("ldmatrix.sync.aligned.m8n8.x4.shared.b16 {%0,%1,%2,%3}, [%4];"
                 : "=r"(r0), "=r"(r1), "=r"(r2), "=r"(r3) : "r"(addr));
}

__device__ __forceinline__ void mma16816(float* c, uint32_t a0, uint32_t a1, uint32_t a2,
                                         uint32_t a3, uint32_t b0, uint32_t b1) {
    asm volatile("mma.sync.aligned.m16n8k16.row.col.f32.f16.f16.f32 "
                 "{%0,%1,%2,%3}, {%4,%5,%6,%7}, {%8,%9}, {%0,%1,%2,%3};"
                 : "+f"(c[0]), "+f"(c[1]), "+f"(c[2]), "+f"(c[3])
                 : "r"(a0), "r"(a1), "r"(a2), "r"(a3), "r"(b0), "r"(b1));
}

__device__ __forceinline__ void upd3(float& v1, int& i1, float& v2, float d, int c) {
    if (d < v1)      { v2 = v1; v1 = d; i1 = c; }
    else             { v2 = fminf(v2, d); }
}

__device__ __forceinline__ void merge3(float& a1, int& ai, float& a2,
                                       float b1, int bi, float b2) {
    if (b1 < a1 || (b1 == a1 && bi < ai)) {
        a2 = fminf(b2, a1); a1 = b1; ai = bi;
    } else {
        a2 = fminf(a2, b1);
    }
}

// smem (bytes) for k_mma: A 32KB @0, B 3x16KB @32768, enorm 16KB @81920
#define SM_A  0
#define SM_B  32768
#define SM_EN 81920
#define SMEM_MMA_BYTES 98304

// smem (bytes) for k_fixmma: AH 32K, AL 32K, B 2x16K (hi8K+lo8K), rows 512B
// 98816 B/CTA -> 106496 after 8KB granularity; x2 = 212992 < 233472 => 2 CTA/SM
#define SM2_AH   0
#define SM2_AL   32768
#define SM2_B    65536
#define SM2_ROWS 98304
#define SMEM_FIXMMA_BYTES 98816

// ---------------------------------------------------------------------------
// K0: prescale EMA state into output regions, zero accumulators
// ---------------------------------------------------------------------------
__global__ void k_init(const float* __restrict__ cluster_size,
                       const float* __restrict__ embed_avg,
                       float* __restrict__ out) {
    int i = blockIdx.x * 256 + threadIdx.x;
    if (i < DIM * K_CODES) out[OFF_EAVG + i] = embed_avg[i] * DECAY;
    if (i < K_CODES) {
        out[OFF_CS + i] = cluster_size[i] * DECAY;
        g_hist[i] = 0;
        g_cur[i]  = 0;
    }
    if (i < 128) g_losspart[i] = 0.0;
    if (i == 0) { g_fixn = 0; g_fixn2 = 0; }
}

// ---------------------------------------------------------------------------
// K0b: smem-tiled transpose embed -> embedT fp32 / fp16 hi / fp16 lo
// ---------------------------------------------------------------------------
__global__ void k_prepe(const float* __restrict__ embed) {
    __shared__ float t[32][33];
    int k0 = blockIdx.x * 32, d0 = blockIdx.y * 32;
    int tx = threadIdx.x, ty = threadIdx.y;
    #pragma unroll
    for (int j = 0; j < 4; j++)
        t[ty + j * 8][tx] = embed[(size_t)(d0 + ty + j * 8) * K_CODES + k0 + tx];
    __syncthreads();
    #pragma unroll
    for (int j = 0; j < 4; j++) {
        int k = k0 + ty + j * 8;
        float v = t[tx][ty + j * 8];
        size_t o = (size_t)k * DIM + d0 + tx;
        g_embedT[o] = v;
        __half h = __float2half_rn(v);
        g_ehi[o] = h;
        g_elo[o] = __float2half_rn(v - __half2float(h));
    }
}

// ---------------------------------------------------------------------------
// K0c: per-codeword squared norm (exact fp32)
// ---------------------------------------------------------------------------
__global__ void k_enorm() {
    int gid  = blockIdx.x * 256 + threadIdx.x;
    int k    = gid >> 5;
    int lane = gid & 31;
    float4 v = ((const float4*)(g_embedT + k * DIM))[lane];
    float s = v.x * v.x + v.y * v.y + v.z * v.z + v.w * v.w;
    #pragma unroll
    for (int o = 16; o > 0; o >>= 1) s += __shfl_down_sync(0xffffffffu, s, o);
    if (lane == 0) g_enorm[k] = s;
}

// ---------------------------------------------------------------------------
// K1: fp16-hi mma.sync GEMM, 128 rows/block, warp = 32 rows x 32 cols
// (2 CTA/SM) + per-row top-2 argmin (+ margin flag + hist)  [R13 layout]
// ---------------------------------------------------------------------------
__global__ void __launch_bounds__(256, 2)
k_mma(const float* __restrict__ x, float* __restrict__ out) {
    extern __shared__ __align__(16) char smem[];
    const uint32_t sb = s2u(smem);
    const int tid  = threadIdx.x;
    const int warp = tid >> 5;
    const int lane = tid & 31;
    const int g    = lane >> 2;
    const int t4   = lane & 3;
    const int row0 = blockIdx.x * 128;
    const int mq   = warp >> 1;
    const int nh   = warp & 1;

    for (int u = tid; u < 1024; u += 256)
        CP_ASYNC16(sb + SM_EN + u * 16, g_enorm + u * 4);
    CP_COMMIT();

    const float* xb = x + (size_t)row0 * DIM;
    for (int u = tid; u < 2048; u += 256) {
        int r = u >> 4, s = u & 15;
        const float4* src = (const float4*)(xb + r * DIM + s * 8);
        float4 v0 = src[0], v1 = src[1];
        __half2 h0 = __floats2half2_rn(v0.x, v0.y);
        __half2 h1 = __floats2half2_rn(v0.z, v0.w);
        __half2 h2 = __floats2half2_rn(v1.x, v1.y);
        __half2 h3 = __floats2half2_rn(v1.z, v1.w);
        uint4 pk = make_uint4(*(uint32_t*)&h0, *(uint32_t*)&h1, *(uint32_t*)&h2, *(uint32_t*)&h3);
        *(uint4*)(smem + SM_A + r * 256 + ((s ^ (r & 7)) << 4)) = pk;
    }

    #pragma unroll
    for (int pc = 0; pc < 2; pc++) {
        const __half* eh = g_ehi + (size_t)(pc * 64) * DIM;
        uint32_t bb = sb + SM_B + pc * 16384;
        for (int u = tid; u < 1024; u += 256) {
            int n = u >> 4, s = u & 15;
            CP_ASYNC16(bb + n * 256 + ((s ^ (n & 7)) << 4), eh + n * DIM + s * 8);
        }
        CP_COMMIT();
    }

    const int bn   = (lane & 7) + ((lane >> 1) & 8);
    const int bchi = (lane >> 3) & 1;
    const int arow = mq * 32 + (lane & 15);
    const int achi = lane >> 4;
    const uint32_t abase = sb + SM_A + arow * 256;
    const int brow0 = nh * 32 + bn;
    const uint32_t boff = (uint32_t)(brow0 * 256);
    const int bsw = brow0 & 7;
    const int asw = arow & 7;

    float q1[4][2], q2[4][2];
    int   qi[4][2];
    #pragma unroll
    for (int s = 0; s < 4; s++)
        #pragma unroll
        for (int c = 0; c < 2; c++) { q1[s][c] = FLT_MAX; q2[s][c] = FLT_MAX; qi[s][c] = 0; }

    const float* en_s = (const float*)(smem + SM_EN);

    for (int i = 0; i < 64; i++) {
        if (i < 63) CP_WAIT(1); else CP_WAIT(0);
        __syncthreads();
        if (i + 2 < 64) {
            const __half* eh = g_ehi + (size_t)((i + 2) * 64) * DIM;
            uint32_t bb = sb + SM_B + ((i + 2) % 3) * 16384;
            for (int u = tid; u < 1024; u += 256) {
                int n = u >> 4, s = u & 15;
                CP_ASYNC16(bb + n * 256 + ((s ^ (n & 7)) << 4), eh + n * DIM + s * 8);
            }
            CP_COMMIT();
        }

        const uint32_t Bb = sb + SM_B + (i % 3) * 16384 + boff;

        float acc[2][4][4];
        #pragma unroll
        for (int mt = 0; mt < 2; mt++)
            #pragma unroll
            for (int nt = 0; nt < 4; nt++)
                #pragma unroll
                for (int j = 0; j < 4; j++) acc[mt][nt][j] = 0.f;

        #pragma unroll
        for (int ks = 0; ks < 8; ks++) {
            uint32_t aoff = ((ks * 2 + achi) ^ asw) << 4;
            uint32_t a0, a1, a2, a3, a4, a5, a6, a7;
            ldsm_x4(a0, a1, a2, a3, abase + aoff);
            ldsm_x4(a4, a5, a6, a7, abase + 16 * 256 + aoff);
            const uint32_t bsz = ((ks * 2 + bchi) ^ bsw) << 4;
            #pragma unroll
            for (int gi = 0; gi < 2; gi++) {
                uint32_t b0, b1, b2, b3;
                ldsm_x4(b0, b1, b2, b3, Bb + gi * 4096 + bsz);
                mma16816(acc[0][2 * gi],     a0, a1, a2, a3, b0, b1);
                mma16816(acc[0][2 * gi + 1], a0, a1, a2, a3, b2, b3);
                mma16816(acc[1][2 * gi],     a4, a5, a6, a7, b0, b1);
                mma16816(acc[1][2 * gi + 1], a4, a5, a6, a7, b2, b3);
            }
        }

        int c0 = i * 64 + nh * 32;
        #pragma unroll
        for (int gi = 0; gi < 2; gi++) {
            #pragma unroll
            for (int h = 0; h < 2; h++) {
                int col = c0 + gi * 16 + h * 8 + t4 * 2;
                float2 en2 = *(const float2*)(en_s + col);
                #pragma unroll
                for (int mt = 0; mt < 2; mt++) {
                    float d0 = fmaf(-2.f, acc[mt][2 * gi + h][0], en2.x);
                    float d1 = fmaf(-2.f, acc[mt][2 * gi + h][1], en2.y);
                    float d2 = fmaf(-2.f, acc[mt][2 * gi + h][2], en2.x);
                    float d3 = fmaf(-2.f, acc[mt][2 * gi + h][3], en2.y);
                    upd3(q1[mt * 2][h],     qi[mt * 2][h],     q2[mt * 2][h],     d0, col);
                    upd3(q1[mt * 2][h],     qi[mt * 2][h],     q2[mt * 2][h],     d1, col + 1);
                    upd3(q1[mt * 2 + 1][h], qi[mt * 2 + 1][h], q2[mt * 2 + 1][h], d2, col);
                    upd3(q1[mt * 2 + 1][h], qi[mt * 2 + 1][h], q2[mt * 2 + 1][h], d3, col + 1);
                }
            }
        }
    }

    float fv1[4], fv2[4]; int fi1[4];
    #pragma unroll
    for (int s = 0; s < 4; s++) {
        fv1[s] = q1[s][0]; fv2[s] = q2[s][0]; fi1[s] = qi[s][0];
        merge3(fv1[s], fi1[s], fv2[s], q1[s][1], qi[s][1], q2[s][1]);
        #pragma unroll
        for (int m = 1; m <= 2; m <<= 1) {
            float ov1 = __shfl_xor_sync(0xffffffffu, fv1[s], m);
            int   oi1 = __shfl_xor_sync(0xffffffffu, fi1[s], m);
            float ov2 = __shfl_xor_sync(0xffffffffu, fv2[s], m);
            merge3(fv1[s], fi1[s], fv2[s], ov1, oi1, ov2);
        }
    }

    float* sv1 = (float*)(smem + SM_EN);
    float* sv2 = (float*)(smem + SM_EN + 1024);
    int*   si1 = (int*)(smem + SM_EN + 2048);
    __syncthreads();
    if (t4 == 0) {
        #pragma unroll
        for (int s = 0; s < 4; s++) {
            int rl = mq * 32 + (s >> 1) * 16 + (s & 1) * 8 + g;
            sv1[nh * 128 + rl] = fv1[s];
            sv2[nh * 128 + rl] = fv2[s];
            si1[nh * 128 + rl] = fi1[s];
        }
    }
    __syncthreads();
    if (tid < 128) {
        float v1 = sv1[tid], v2 = sv2[tid]; int i1 = si1[tid];
        merge3(v1, i1, v2, sv1[128 + tid], si1[128 + tid], sv2[128 + tid]);
        int row = row0 + tid;
        out[OFF_IND + row] = (float)i1;
        atomicAdd(&g_hist[i1], 1);
        if (v2 - v1 < MARGIN) {
            int p = atomicAdd(&g_fixn, 1);
            if (p < FIX_CAP) g_fixlist[p] = row;
        }
    }
}

// ---------------------------------------------------------------------------
// K1b: split-fp16 3-term mma rescue; item = (128-row tile, 1024-code quarter)
// 32-code chunks, 2-stage buffer, 2 CTA/SM (smem verified vs 8KB granularity)
// ---------------------------------------------------------------------------
__global__ void __launch_bounds__(256, 2)
k_fixmma(const float* __restrict__ x) {
    extern __shared__ __align__(16) char smem[];
    const uint32_t sb = s2u(smem);
    const int tid  = threadIdx.x;
    const int warp = tid >> 5;
    const int lane = tid & 31;
    const int g    = lane >> 2;
    const int t4   = lane & 3;

    int nfix = g_fixn;
    if (nfix > FIX_CAP) nfix = FIX_CAP;
    if (nfix == 0) return;
    const int nrt = (nfix + 127) >> 7;
    const int nitems = nrt * 4;

    int* rowmap = (int*)(smem + SM2_ROWS);

    const int bn   = (lane & 7) + ((lane >> 1) & 8);
    const int bchi = (lane >> 3) & 1;
    const int arow = warp * 16 + (lane & 15);
    const int achi = lane >> 4;
    const uint32_t ahbase = sb + SM2_AH + arow * 256;
    const uint32_t albase = sb + SM2_AL + arow * 256;
    const uint32_t boff   = (uint32_t)(bn * 256);
    const int bsw = bn & 7;
    const int asw = arow & 7;

    for (int item = blockIdx.x; item < nitems; item += gridDim.x) {
        const int tile = item >> 2;
        const int cq   = item & 3;
        __syncthreads();
        if (tid < 128) {
            int j = tile * 128 + tid;
            rowmap[tid] = g_fixlist[(j < nfix) ? j : (nfix - 1)];
        }
        __syncthreads();

        // gather + convert A (hi & lo)
        for (int u = tid; u < 2048; u += 256) {
            int r = u >> 4, s = u & 15;
            const float4* src = (const float4*)(x + (size_t)rowmap[r] * DIM + s * 8);
            float4 v0 = src[0], v1 = src[1];
            __half2 h0 = __floats2half2_rn(v0.x, v0.y);
            __half2 h1 = __floats2half2_rn(v0.z, v0.w);
            __half2 h2 = __floats2half2_rn(v1.x, v1.y);
            __half2 h3 = __floats2half2_rn(v1.z, v1.w);
            __half2 l0 = __floats2half2_rn(v0.x - __low2float(h0), v0.y - __high2float(h0));
            __half2 l1 = __floats2half2_rn(v0.z - __low2float(h1), v0.w - __high2float(h1));
            __half2 l2 = __floats2half2_rn(v1.x - __low2float(h2), v1.y - __high2float(h2));
            __half2 l3 = __floats2half2_rn(v1.z - __low2float(h3), v1.w - __high2float(h3));
            uint32_t sw = r * 256 + ((s ^ (r & 7)) << 4);
            *(uint4*)(smem + SM2_AH + sw) = make_uint4(*(uint32_t*)&h0, *(uint32_t*)&h1,
                                                       *(uint32_t*)&h2, *(uint32_t*)&h3);
            *(uint4*)(smem + SM2_AL + sw) = make_uint4(*(uint32_t*)&l0, *(uint32_t*)&l1,
                                                       *(uint32_t*)&l2, *(uint32_t*)&l3);
        }

        // prefetch chunk 0 (32 codes, hi+lo) into stage 0
        {
            const __half* eh = g_ehi + (size_t)(cq * 1024) * DIM;
            const __half* el = g_elo + (size_t)(cq * 1024) * DIM;
            uint32_t bb = sb + SM2_B;
            for (int u = tid; u < 512; u += 256) {
                int n = u >> 4, s = u & 15;
                uint32_t sw = n * 256 + ((s ^ (n & 7)) << 4);
                CP_ASYNC16(bb + sw,        eh + n * DIM + s * 8);
                CP_ASYNC16(bb + 8192 + sw, el + n * DIM + s * 8);
            }
            CP_COMMIT();
        }

        float cav1[2], cav2[2], cbv1[2], cbv2[2];
        int   cai[2], cbi[2];
        #pragma unroll
        for (int k = 0; k < 2; k++) {
            cav1[k] = FLT_MAX; cav2[k] = FLT_MAX; cai[k] = 0;
            cbv1[k] = FLT_MAX; cbv2[k] = FLT_MAX; cbi[k] = 0;
        }

        for (int i = 0; i < 32; i++) {
            CP_WAIT(0);
            __syncthreads();
            if (i + 1 < 32) {
                const __half* eh = g_ehi + (size_t)(cq * 1024 + (i + 1) * 32) * DIM;
                const __half* el = g_elo + (size_t)(cq * 1024 + (i + 1) * 32) * DIM;
                uint32_t bb = sb + SM2_B + ((i + 1) & 1) * 16384;
                for (int u = tid; u < 512; u += 256) {
                    int n = u >> 4, s = u & 15;
                    uint32_t sw = n * 256 + ((s ^ (n & 7)) << 4);
                    CP_ASYNC16(bb + sw,        eh + n * DIM + s * 8);
                    CP_ASYNC16(bb + 8192 + sw, el + n * DIM + s * 8);
                }
                CP_COMMIT();
            }

            const uint32_t Bh = sb + SM2_B + (i & 1) * 16384 + boff;
            const uint32_t Bl = Bh + 8192;

            float acc[4][4];
            #pragma unroll
            for (int nt = 0; nt < 4; nt++)
                #pragma unroll
                for (int j = 0; j < 4; j++) acc[nt][j] = 0.f;

            #pragma unroll
            for (int ks = 0; ks < 8; ks++) {
                uint32_t ah0, ah1, ah2, ah3, al0, al1, al2, al3;
                uint32_t aoff = ((ks * 2 + achi) ^ asw) << 4;
                ldsm_x4(ah0, ah1, ah2, ah3, ahbase + aoff);
                ldsm_x4(al0, al1, al2, al3, albase + aoff);
                const uint32_t bsz = ((ks * 2 + bchi) ^ bsw) << 4;
                #pragma unroll
                for (int gi = 0; gi < 2; gi++) {
                    uint32_t bh0, bh1, bh2, bh3, bl0, bl1, bl2, bl3;
                    ldsm_x4(bh0, bh1, bh2, bh3, Bh + gi * 4096 + bsz);
                    ldsm_x4(bl0, bl1, bl2, bl3, Bl + gi * 4096 + bsz);
                    mma16816(acc[2 * gi],     ah0, ah1, ah2, ah3, bh0, bh1);
                    mma16816(acc[2 * gi],     ah0, ah1, ah2, ah3, bl0, bl1);
                    mma16816(acc[2 * gi],     al0, al1, al2, al3, bh0, bh1);
                    mma16816(acc[2 * gi + 1], ah0, ah1, ah2, ah3, bh2, bh3);
                    mma16816(acc[2 * gi + 1], ah0, ah1, ah2, ah3, bl2, bl3);
                    mma16816(acc[2 * gi + 1], al0, al1, al2, al3, bh2, bh3);
                }
            }

            int c0 = cq * 1024 + i * 32;
            #pragma unroll
            for (int nt = 0; nt < 4; nt++) {
                int ch  = nt & 1;
                int col = c0 + nt * 8 + t4 * 2;
                float2 en2 = __ldg((const float2*)(g_enorm + col));
                float d0 = fmaf(-2.f, acc[nt][0], en2.x);
                float d1 = fmaf(-2.f, acc[nt][1], en2.y);
                float d2 = fmaf(-2.f, acc[nt][2], en2.x);
                float d3 = fmaf(-2.f, acc[nt][3], en2.y);
                upd3(cav1[ch], cai[ch], cav2[ch], d0, col);
                upd3(cav1[ch], cai[ch], cav2[ch], d1, col + 1);
                upd3(cbv1[ch], cbi[ch], cbv2[ch], d2, col);
                upd3(cbv1[ch], cbi[ch], cbv2[ch], d3, col + 1);
            }
        }

        float va1 = cav1[0], va2 = cav2[0]; int ia1 = cai[0];
        float vb1 = cbv1[0], vb2 = cbv2[0]; int ib1 = cbi[0];
        merge3(va1, ia1, va2, cav1[1], cai[1], cav2[1]);
        merge3(vb1, ib1, vb2, cbv1[1], cbi[1], cbv2[1]);
        #pragma unroll
        for (int m = 1; m <= 2; m <<= 1) {
            float ov1 = __shfl_xor_sync(0xffffffffu, va1, m);
            int   oi1 = __shfl_xor_sync(0xffffffffu, ia1, m);
            float ov2 = __shfl_xor_sync(0xffffffffu, va2, m);
            merge3(va1, ia1, va2, ov1, oi1, ov2);
            ov1 = __shfl_xor_sync(0xffffffffu, vb1, m);
            oi1 = __shfl_xor_sync(0xffffffffu, ib1, m);
            ov2 = __shfl_xor_sync(0xffffffffu, vb2, m);
            merge3(vb1, ib1, vb2, ov1, oi1, ov2);
        }

        if (t4 == 0) {
            int rlA = warp * 16 + g;
            int rlB = rlA + 8;
            int jA = tile * 128 + rlA;
            int jB = tile * 128 + rlB;
            if (jA < nfix) {
                g_qv1[jA * 4 + cq] = va1; g_qv2[jA * 4 + cq] = va2; g_qi1[jA * 4 + cq] = ia1;
            }
            if (jB < nfix) {
                g_qv1[jB * 4 + cq] = vb1; g_qv2[jB * 4 + cq] = vb2; g_qi1[jB * 4 + cq] = ib1;
            }
        }
    }
}

// ---------------------------------------------------------------------------
// K1c: merge 4 quarter-partials per flagged row; tier decision
// ---------------------------------------------------------------------------
__global__ void k_fixsel(float* __restrict__ out) {
    int nfix = g_fixn;
    if (nfix > FIX_CAP) nfix = FIX_CAP;
    int j = blockIdx.x * 256 + threadIdx.x;
    if (j >= nfix) return;
    float b1 = g_qv1[j * 4], b2 = g_qv2[j * 4]; int bi = g_qi1[j * 4];
    #pragma unroll
    for (int c = 1; c < 4; c++)
        merge3(b1, bi, b2, g_qv1[j * 4 + c], g_qi1[j * 4 + c], g_qv2[j * 4 + c]);
    int row = g_fixlist[j];
    if (b2 - b1 < MARGIN2) {
        int p = atomicAdd(&g_fixn2, 1);
        if (p < FIX2_CAP) g_fixlist2[p] = row;
    } else {
        int old = (int)out[OFF_IND + row];
        if (old != bi) {
            out[OFF_IND + row] = (float)bi;
            atomicAdd(&g_hist[old], -1);
            atomicAdd(&g_hist[bi], 1);
        }
    }
}

// ---------------------------------------------------------------------------
// K1d: exact fp32 partial rescan over SECOND-level list (tiny)
// ---------------------------------------------------------------------------
__global__ void __launch_bounds__(256)
k_fixpart(const float* __restrict__ x) {
    __shared__ float xs[16 * 132];
    __shared__ float cs[2][32 * 132];
    __shared__ float rbv[16 * 8];
    __shared__ int   rbi[16 * 8];
    __shared__ int   rowids[16];
    const uint32_t cs0 = s2u(&cs[0][0]);
    const uint32_t cs1 = s2u(&cs[1][0]);

    int nfix = g_fixn2;
    if (nfix > FIX2_CAP) nfix = FIX2_CAP;
    if (nfix == 0) return;
    const int nrg = (nfix + 15) >> 4;
    const int nitems = nrg * 8;

    const int tid  = threadIdx.x;
    const int ds   = tid & 3;
    const int tile = tid >> 2;
    const int tr   = tile >> 3;
    const int tc   = tile & 7;

    for (int item = blockIdx.x; item < nitems; item += gridDim.x) {
        const int rg = item >> 3;
        const int cg = item & 7;
        const int base = rg * 16;

        if (tid < 16) {
            int j = base + tid;
            rowids[tid] = g_fixlist2[(j < nfix) ? j : (nfix - 1)];
        }
        __syncthreads();
        for (int u = tid; u < 512; u += 256) {
            int r = u >> 5, q = u & 31;
            float4 v = ((const float4*)(x + (size_t)rowids[r] * DIM))[q];
            *(float4*)(xs + r * 132 + q * 4) = v;
        }
        {
            const float* src = g_embedT + (size_t)(cg * 512) * DIM;
            for (int u = tid; u < 1024; u += 256) {
                int c = u >> 5, q = u & 31;
                CP_ASYNC16(cs0 + (uint32_t)(c * 528 + q * 16), src + (size_t)c * DIM + q * 4);
            }
            CP_COMMIT();
        }

        float bv[2]; int bi[2];
        bv[0] = bv[1] = FLT_MAX; bi[0] = bi[1] = 0;

        for (int ci = 0; ci < 16; ci++) {
            CP_WAIT(0);
            __syncthreads();
            if (ci + 1 < 16) {
                uint32_t dst = ((ci + 1) & 1) ? cs1 : cs0;
                const float* src = g_embedT + (size_t)(cg * 512 + (ci + 1) * 32) * DIM;
                for (int u = tid; u < 1024; u += 256) {
                    int c = u >> 5, q = u & 31;
                    CP_ASYNC16(dst + (uint32_t)(c * 528 + q * 16), src + (size_t)c * DIM + q * 4);
                }
                CP_COMMIT();
            }
            const float* csb = cs[ci & 1];

            float acc[2][4];
            #pragma unroll
            for (int rr = 0; rr < 2; rr++)
                #pragma unroll
                for (int cc = 0; cc < 4; cc++) acc[rr][cc] = 0.f;

            #pragma unroll
            for (int d4 = 0; d4 < 8; d4++) {
                int d = ds * 32 + d4 * 4;
                float4 cv[4], rv[2];
                #pragma unroll
                for (int cc = 0; cc < 4; cc++) cv[cc] = *(const float4*)(csb + (tc * 4 + cc) * 132 + d);
                #pragma unroll
                for (int rr = 0; rr < 2; rr++) rv[rr] = *(const float4*)(xs + (tr * 2 + rr) * 132 + d);
                #pragma unroll
                for (int rr = 0; rr < 2; rr++)
                    #pragma unroll
                    for (int cc = 0; cc < 4; cc++)
                        acc[rr][cc] += rv[rr].x * cv[cc].x + rv[rr].y * cv[cc].y +
                                       rv[rr].z * cv[cc].z + rv[rr].w * cv[cc].w;
            }
            #pragma unroll
            for (int rr = 0; rr < 2; rr++)
                #pragma unroll
                for (int cc = 0; cc < 4; cc++) {
                    float a = acc[rr][cc];
                    a += __shfl_xor_sync(0xffffffffu, a, 1);
                    a += __shfl_xor_sync(0xffffffffu, a, 2);
                    acc[rr][cc] = a;
                }
            #pragma unroll
            for (int cc = 0; cc < 4; cc++) {
                int code = cg * 512 + ci * 32 + tc * 4 + cc;
                float en = __ldg(g_enorm + code);
                #pragma unroll
                for (int rr = 0; rr < 2; rr++) {
                    float dv = fmaf(-2.f, acc[rr][cc], en);
                    if (dv < bv[rr]) { bv[rr] = dv; bi[rr] = code; }
                }
            }
        }
        __syncthreads();
        if (ds == 0) {
            #pragma unroll
            for (int rr = 0; rr < 2; rr++) {
                rbv[(tr * 2 + rr) * 8 + tc] = bv[rr];
                rbi[(tr * 2 + rr) * 8 + tc] = bi[rr];
            }
        }
        __syncthreads();
        if (tid < 16) {
            float b = rbv[tid * 8]; int bidx = rbi[tid * 8];
            #pragma unroll
            for (int j = 1; j < 8; j++) {
                float v = rbv[tid * 8 + j]; int idx = rbi[tid * 8 + j];
                if (v < b || (v == b && idx < bidx)) { b = v; bidx = idx; }
            }
            g_pv[(base + tid) * 8 + cg] = b;
            g_pi[(base + tid) * 8 + cg] = bidx;
        }
        __syncthreads();
    }
}

// ---------------------------------------------------------------------------
// K1e: merge exact partials for level-2 rows; adjust out + hist
// ---------------------------------------------------------------------------
__global__ void k_fixmerge(float* __restrict__ out) {
    int nfix = g_fixn2;
    if (nfix > FIX2_CAP) nfix = FIX2_CAP;
    int j = blockIdx.x * 256 + threadIdx.x;
    if (j >= nfix) return;
    float b = g_pv[j * 8]; int bidx = g_pi[j * 8];
    #pragma unroll
    for (int c = 1; c < 8; c++) {
        float v = g_pv[j * 8 + c]; int idx = g_pi[j * 8 + c];
        if (v < b || (v == b && idx < bidx)) { b = v; bidx = idx; }
    }
    int row = g_fixlist2[j];
    int old = (int)out[OFF_IND + row];
    if (old != bidx) {
        out[OFF_IND + row] = (float)bidx;
        atomicAdd(&g_hist[old], -1);
        atomicAdd(&g_hist[bidx], 1);
    }
}

// ---------------------------------------------------------------------------
// K2: prefix sum over hist -> offsets; cluster_size_new; n; n_small
// ---------------------------------------------------------------------------
__global__ void k_prefix(float* __restrict__ out) {
    __shared__ int   wsum[32];
    __shared__ float fsum[32];
    __shared__ int   fcnt[32];
    int t = threadIdx.x;
    int h0 = g_hist[t * 4], h1 = g_hist[t * 4 + 1], h2 = g_hist[t * 4 + 2], h3 = g_hist[t * 4 + 3];
    int loc = h0 + h1 + h2 + h3;
    int pre = loc;
    #pragma unroll
    for (int o = 1; o < 32; o <<= 1) {
        int n = __shfl_up_sync(0xffffffffu, pre, o);
        if ((t & 31) >= o) pre += n;
    }
    if ((t & 31) == 31) wsum[t >> 5] = pre;
    __syncthreads();
    if (t < 32) {
        int v = wsum[t];
        #pragma unroll
        for (int o = 1; o < 32; o <<= 1) {
            int n = __shfl_up_sync(0xffffffffu, v, o);
            if (t >= o) v += n;
        }
        wsum[t] = v;
    }
    __syncthreads();
    int base = pre - loc + ((t >= 32) ? wsum[(t >> 5) - 1] : 0);
    g_off[t * 4]     = base;
    g_off[t * 4 + 1] = base + h0;
    g_off[t * 4 + 2] = base + h0 + h1;
    g_off[t * 4 + 3] = base + h0 + h1 + h2;
    float c0 = out[OFF_CS + t * 4]     + ONE_M_D * (float)h0;
    float c1 = out[OFF_CS + t * 4 + 1] + ONE_M_D * (float)h1;
    float c2 = out[OFF_CS + t * 4 + 2] + ONE_M_D * (float)h2;
    float c3 = out[OFF_CS + t * 4 + 3] + ONE_M_D * (float)h3;
    out[OFF_CS + t * 4]     = c0;
    out[OFF_CS + t * 4 + 1] = c1;
    out[OFF_CS + t * 4 + 2] = c2;
    out[OFF_CS + t * 4 + 3] = c3;
    float s = c0 + c1 + c2 + c3;
    int   c = (c0 < 1.f) + (c1 < 1.f) + (c2 < 1.f) + (c3 < 1.f);
    #pragma unroll
    for (int o = 16; o > 0; o >>= 1) {
        s += __shfl_down_sync(0xffffffffu, s, o);
        c += __shfl_down_sync(0xffffffffu, c, o);
    }
    if ((t & 31) == 0) { fsum[t >> 5] = s; fcnt[t >> 5] = c; }
    __syncthreads();
    if (t < 32) {
        s = fsum[t]; c = fcnt[t];
        #pragma unroll
        for (int o = 16; o > 0; o >>= 1) {
            s += __shfl_down_sync(0xffffffffu, s, o);
            c += __shfl_down_sync(0xffffffffu, c, o);
        }
        if (t == 0) { g_n = s; out[OFF_NSMALL] = (float)c; }
    }
}

// ---------------------------------------------------------------------------
// K2c: bin rows by code (barrier-free)
// ---------------------------------------------------------------------------
__global__ void k_scatter(const float* __restrict__ out_c) {
    int i = blockIdx.x * 256 + threadIdx.x;
    if (i >= N_ROWS) return;
    int idx = (int)out_c[OFF_IND + i];
    int pos = atomicAdd(&g_cur[idx], 1);
    g_rowlist[g_off[idx] + pos] = i;
}

// ---------------------------------------------------------------------------
// K2d: per-code gather-sum into embed_avg_new (one warp per code)
// ---------------------------------------------------------------------------
__global__ void __launch_bounds__(256)
k_avg(const float* __restrict__ x, float* __restrict__ out) {
    int c    = blockIdx.x * 8 + (threadIdx.x >> 5);
    int lane = threadIdx.x & 31;
    int cnt  = g_hist[c];
    int base = g_off[c];
    float4 s = make_float4(0.f, 0.f, 0.f, 0.f);
    for (int j = 0; j < cnt; j++) {
        int r = g_rowlist[base + j];
        float4 v = ((const float4*)(x + (size_t)r * DIM))[lane];
        s.x += v.x; s.y += v.y; s.z += v.z; s.w += v.w;
    }
    if (cnt > 0) {
        out[OFF_EAVG + (size_t)(lane * 4 + 0) * K_CODES + c] += ONE_M_D * s.x;
        out[OFF_EAVG + (size_t)(lane * 4 + 1) * K_CODES + c] += ONE_M_D * s.y;
        out[OFF_EAVG + (size_t)(lane * 4 + 2) * K_CODES + c] += ONE_M_D * s.z;
        out[OFF_EAVG + (size_t)(lane * 4 + 3) * K_CODES + c] += ONE_M_D * s.w;
    }
}

// ---------------------------------------------------------------------------
// K3: quantize gather + loss (all rows, final indices; spread atomic slots)
// ---------------------------------------------------------------------------
__global__ void __launch_bounds__(256)
k_post(const float* __restrict__ x, float* __restrict__ out) {
    __shared__ float wls[8];
    int warp = threadIdx.x >> 5;
    int lane = threadIdx.x & 31;
    int row  = blockIdx.x * 8 + warp;
    int idx  = (int)out[OFF_IND + row];
    float4 q  = ((const float4*)(g_embedT + (size_t)idx * DIM))[lane];
    float4 xv = ((const float4*)(x + (size_t)row * DIM))[lane];
    ((float4*)(out + OFF_Q + (size_t)row * DIM))[lane] = q;
    float d0 = q.x - xv.x, d1 = q.y - xv.y, d2 = q.z - xv.z, d3 = q.w - xv.w;
    float lsum = d0 * d0 + d1 * d1 + d2 * d2 + d3 * d3;
    #pragma unroll
    for (int o = 16; o > 0; o >>= 1) lsum += __shfl_down_sync(0xffffffffu, lsum, o);
    if (lane == 0) wls[warp] = lsum;
    __syncthreads();
    if (threadIdx.x == 0) {
        float b = wls[0] + wls[1] + wls[2] + wls[3] + wls[4] + wls[5] + wls[6] + wls[7];
        atomicAdd(&g_losspart[blockIdx.x & 127], (double)b);
    }
}

// ---------------------------------------------------------------------------
// K5: embed_new = embed_avg_new / cs_norm; finalize loss
// ---------------------------------------------------------------------------
__global__ void k_final(float* __restrict__ out) {
    int i = blockIdx.x * 256 + threadIdx.x;
    if (i < DIM * K_CODES) {
        int k = i & (K_CODES - 1);
        float n   = g_n;
        float cs  = out[OFF_CS + k];
        float csn = (cs + EPS) / (n + (float)K_CODES * EPS) * n;
        out[OFF_ENEW + i] = out[OFF_EAVG + i] / csn;
    }
    if (blockIdx.x == 0 && threadIdx.x == 0) {
        double tot = 0.0;
        #pragma unroll
        for (int j = 0; j < 128; j++) tot += g_losspart[j];
        out[OFF_LOSS] = (float)(tot / ((double)N_ROWS * (double)DIM));
    }
}

// ---------------------------------------------------------------------------
extern "C" void kernel_launch(void* const* d_in, const int* in_sizes, int n_in,
                              void* d_out, int out_size) {
    const float* x            = (const float*)d_in[0];
    const float* embed        = (const float*)d_in[1];
    const float* cluster_size = (const float*)d_in[2];
    const float* embed_avg    = (const float*)d_in[3];
    float* out = (float*)d_out;

    cudaFuncSetAttribute(k_mma, cudaFuncAttributeMaxDynamicSharedMemorySize, SMEM_MMA_BYTES);
    cudaFuncSetAttribute(k_fixmma, cudaFuncAttributeMaxDynamicSharedMemorySize, SMEM_FIXMMA_BYTES);

    k_init<<<(DIM * K_CODES + 255) / 256, 256>>>(cluster_size, embed_avg, out);
    k_prepe<<<dim3(K_CODES / 32, DIM / 32), dim3(32, 8)>>>(embed);
    k_enorm<<<(K_CODES * 32) / 256, 256>>>();
    k_mma<<<N_ROWS / 128, 256, SMEM_MMA_BYTES>>>(x, out);
    k_fixmma<<<592, 256, SMEM_FIXMMA_BYTES>>>(x);
    k_fixsel<<<FIX_CAP / 256, 256>>>(out);
    k_fixpart<<<256, 256>>>(x);
    k_fixmerge<<<FIX2_CAP / 256, 256>>>(out);
    k_prefix<<<1, 1024>>>(out);
    k_scatter<<<N_ROWS / 256, 256>>>(out);
    k_avg<<<K_CODES / 8, 256>>>(x, out);
    k_post<<<N_ROWS / 8, 256>>>(x, out);
    k_final<<<(DIM * K_CODES + 255) / 256, 256>>>(out);
}

// round 16
// speedup vs baseline: 1.0090x; 1.0090x over previous
#include <cuda_runtime.h>
#include <cuda_fp16.h>
#include <float.h>
#include <stdint.h>

#define N_ROWS   131072
#define DIM      128
#define K_CODES  4096
#define DECAY    0.99f
#define ONE_M_D  0.01f
#define EPS      1e-5f
#define MARGIN   0.08f
#define MARGIN2  2e-3f
#define FIX_CAP  32768
#define FIX2_CAP 8192

// Output layout (tuple order, flattened, f32)
#define OFF_Q      0
#define OFF_LOSS   16777216
#define OFF_NSMALL 16777217
#define OFF_IND    16777218
#define OFF_ENEW   16908290
#define OFF_CS     17432578
#define OFF_EAVG   17436674

// ---------------- device scratch (no allocation) ----------------
__device__ __align__(16) float  g_embedT[K_CODES * DIM];
__device__ __align__(16) __half g_ehi[K_CODES * DIM];
__device__ __align__(16) __half g_elo[K_CODES * DIM];
__device__ __align__(16) float  g_enorm[K_CODES];
__device__ double g_losspart[128];
__device__ float  g_n;
__device__ int    g_fixn;
__device__ int    g_fixlist[FIX_CAP];
__device__ int    g_fixn2;
__device__ int    g_fixlist2[FIX2_CAP];
__device__ float  g_qv1[FIX_CAP * 4];
__device__ float  g_qv2[FIX_CAP * 4];
__device__ int    g_qi1[FIX_CAP * 4];
__device__ int    g_qcnt[FIX_CAP];
__device__ float  g_pv[(FIX2_CAP + 16) * 8];
__device__ int    g_pi[(FIX2_CAP + 16) * 8];
__device__ int    g_cnt2[FIX2_CAP / 16 + 1];
__device__ int    g_hist[K_CODES];
__device__ int    g_off[K_CODES];
__device__ int    g_cur[K_CODES];
__device__ int    g_rowlist[N_ROWS];

// ---------------- helpers ----------------
#define CP_ASYNC16(dst, src) \
    asm volatile("cp.async.cg.shared.global [%0], [%1], 16;" :: "r"(dst), "l"(src) : "memory")
#define CP_COMMIT() asm volatile("cp.async.commit_group;" ::: "memory")
#define CP_WAIT(n)  asm volatile("cp.async.wait_group %0;" :: "n"(n) : "memory")

__device__ __forceinline__ uint32_t s2u(const void* p) {
    uint32_t a;
    asm("{ .reg .u64 t; cvta.to.shared.u64 t, %1; cvt.u32.u64 %0, t; }" : "=r"(a) : "l"(p));
    return a;
}

__device__ __forceinline__ void ldsm_x4(uint32_t& r0, uint32_t& r1, uint32_t& r2, uint32_t& r3,
                                        uint32_t addr) {
    asm volatile("ldmatrix.sync.aligned.m8n8.x4.shared.b16 {%0,%1,%2,%3}, [%4];"
                 : "=r"(r0), "=r"(r1), "=r"(r2), "=r"(r3) : "r"(addr));
}

__device__ __forceinline__ void mma16816(float* c, uint32_t a0, uint32_t a1, uint32_t a2,
                                         uint32_t a3, uint32_t b0, uint32_t b1) {
    asm volatile("mma.sync.aligned.m16n8k16.row.col.f32.f16.f16.f32 "
                 "{%0,%1,%2,%3}, {%4,%5,%6,%7}, {%8,%9}, {%0,%1,%2,%3};"
                 : "+f"(c[0]), "+f"(c[1]), "+f"(c[2]), "+f"(c[3])
                 : "r"(a0), "r"(a1), "r"(a2), "r"(a3), "r"(b0), "r"(b1));
}

__device__ __forceinline__ void upd3(float& v1, int& i1, float& v2, float d, int c) {
    if (d < v1)      { v2 = v1; v1 = d; i1 = c; }
    else             { v2 = fminf(v2, d); }
}

__device__ __forceinline__ void merge3(float& a1, int& ai, float& a2,
                                       float b1, int bi, float b2) {
    if (b1 < a1 || (b1 == a1 && bi < ai)) {
        a2 = fminf(b2, a1); a1 = b1; ai = bi;
    } else {
        a2 = fminf(a2, b1);
    }
}

// smem (bytes) for k_mma: A 32KB @0, B 3x16KB @32768, enorm 16KB @81920
#define SM_A  0
#define SM_B  32768
#define SM_EN 81920
#define SMEM_MMA_BYTES 98304

// smem (bytes) for k_fixmma (R14-proven: 64-code chunks, double buffer)
#define SM2_AH   0
#define SM2_AL   32768
#define SM2_B    65536
#define SM2_EN   131072
#define SM2_ROWS 147456
#define SMEM_FIXMMA_BYTES 147968

// ---------------------------------------------------------------------------
// K0: prescale EMA state into output regions, zero accumulators
// ---------------------------------------------------------------------------
__global__ void k_init(const float* __restrict__ cluster_size,
                       const float* __restrict__ embed_avg,
                       float* __restrict__ out) {
    int i = blockIdx.x * 256 + threadIdx.x;
    if (i < DIM * K_CODES) out[OFF_EAVG + i] = embed_avg[i] * DECAY;
    if (i < K_CODES) {
        out[OFF_CS + i] = cluster_size[i] * DECAY;
        g_hist[i]  = 0;
        g_cur[i]   = 0;
        g_enorm[i] = 0.f;
    }
    if (i < FIX_CAP) g_qcnt[i] = 0;
    if (i < FIX2_CAP / 16 + 1) g_cnt2[i] = 0;
    if (i < 128) g_losspart[i] = 0.0;
    if (i == 0) { g_fixn = 0; g_fixn2 = 0; }
}

// ---------------------------------------------------------------------------
// K0b: smem-tiled transpose embed -> embedT fp32 / fp16 hi / fp16 lo
//      + fused partial enorm (warp reduce + atomicAdd)
// ---------------------------------------------------------------------------
__global__ void k_prepe(const float* __restrict__ embed) {
    __shared__ float t[32][33];
    int k0 = blockIdx.x * 32, d0 = blockIdx.y * 32;
    int tx = threadIdx.x, ty = threadIdx.y;
    #pragma unroll
    for (int j = 0; j < 4; j++)
        t[ty + j * 8][tx] = embed[(size_t)(d0 + ty + j * 8) * K_CODES + k0 + tx];
    __syncthreads();
    #pragma unroll
    for (int j = 0; j < 4; j++) {
        int k = k0 + ty + j * 8;
        float v = t[tx][ty + j * 8];
        size_t o = (size_t)k * DIM + d0 + tx;
        g_embedT[o] = v;
        __half h = __float2half_rn(v);
        g_ehi[o] = h;
        g_elo[o] = __float2half_rn(v - __half2float(h));
        float sq = v * v;
        #pragma unroll
        for (int of = 16; of > 0; of >>= 1) sq += __shfl_down_sync(0xffffffffu, sq, of);
        if (tx == 0) atomicAdd(&g_enorm[k], sq);
    }
}

// ---------------------------------------------------------------------------
// K1: fp16-hi mma.sync GEMM, 128 rows/block, warp = 32 rows x 32 cols
// (2 CTA/SM) + per-row top-2 argmin (+ margin flag + hist)  [R13 layout]
// ---------------------------------------------------------------------------
__global__ void __launch_bounds__(256, 2)
k_mma(const float* __restrict__ x, float* __restrict__ out) {
    extern __shared__ __align__(16) char smem[];
    const uint32_t sb = s2u(smem);
    const int tid  = threadIdx.x;
    const int warp = tid >> 5;
    const int lane = tid & 31;
    const int g    = lane >> 2;
    const int t4   = lane & 3;
    const int row0 = blockIdx.x * 128;
    const int mq   = warp >> 1;
    const int nh   = warp & 1;

    for (int u = tid; u < 1024; u += 256)
        CP_ASYNC16(sb + SM_EN + u * 16, g_enorm + u * 4);
    CP_COMMIT();

    const float* xb = x + (size_t)row0 * DIM;
    for (int u = tid; u < 2048; u += 256) {
        int r = u >> 4, s = u & 15;
        const float4* src = (const float4*)(xb + r * DIM + s * 8);
        float4 v0 = src[0], v1 = src[1];
        __half2 h0 = __floats2half2_rn(v0.x, v0.y);
        __half2 h1 = __floats2half2_rn(v0.z, v0.w);
        __half2 h2 = __floats2half2_rn(v1.x, v1.y);
        __half2 h3 = __floats2half2_rn(v1.z, v1.w);
        uint4 pk = make_uint4(*(uint32_t*)&h0, *(uint32_t*)&h1, *(uint32_t*)&h2, *(uint32_t*)&h3);
        *(uint4*)(smem + SM_A + r * 256 + ((s ^ (r & 7)) << 4)) = pk;
    }

    #pragma unroll
    for (int pc = 0; pc < 2; pc++) {
        const __half* eh = g_ehi + (size_t)(pc * 64) * DIM;
        uint32_t bb = sb + SM_B + pc * 16384;
        for (int u = tid; u < 1024; u += 256) {
            int n = u >> 4, s = u & 15;
            CP_ASYNC16(bb + n * 256 + ((s ^ (n & 7)) << 4), eh + n * DIM + s * 8);
        }
        CP_COMMIT();
    }

    const int bn   = (lane & 7) + ((lane >> 1) & 8);
    const int bchi = (lane >> 3) & 1;
    const int arow = mq * 32 + (lane & 15);
    const int achi = lane >> 4;
    const uint32_t abase = sb + SM_A + arow * 256;
    const int brow0 = nh * 32 + bn;
    const uint32_t boff = (uint32_t)(brow0 * 256);
    const int bsw = brow0 & 7;
    const int asw = arow & 7;

    float q1[4][2], q2[4][2];
    int   qi[4][2];
    #pragma unroll
    for (int s = 0; s < 4; s++)
        #pragma unroll
        for (int c = 0; c < 2; c++) { q1[s][c] = FLT_MAX; q2[s][c] = FLT_MAX; qi[s][c] = 0; }

    const float* en_s = (const float*)(smem + SM_EN);

    for (int i = 0; i < 64; i++) {
        if (i < 63) CP_WAIT(1); else CP_WAIT(0);
        __syncthreads();
        if (i + 2 < 64) {
            const __half* eh = g_ehi + (size_t)((i + 2) * 64) * DIM;
            uint32_t bb = sb + SM_B + ((i + 2) % 3) * 16384;
            for (int u = tid; u < 1024; u += 256) {
                int n = u >> 4, s = u & 15;
                CP_ASYNC16(bb + n * 256 + ((s ^ (n & 7)) << 4), eh + n * DIM + s * 8);
            }
            CP_COMMIT();
        }

        const uint32_t Bb = sb + SM_B + (i % 3) * 16384 + boff;

        float acc[2][4][4];
        #pragma unroll
        for (int mt = 0; mt < 2; mt++)
            #pragma unroll
            for (int nt = 0; nt < 4; nt++)
                #pragma unroll
                for (int j = 0; j < 4; j++) acc[mt][nt][j] = 0.f;

        #pragma unroll
        for (int ks = 0; ks < 8; ks++) {
            uint32_t aoff = ((ks * 2 + achi) ^ asw) << 4;
            uint32_t a0, a1, a2, a3, a4, a5, a6, a7;
            ldsm_x4(a0, a1, a2, a3, abase + aoff);
            ldsm_x4(a4, a5, a6, a7, abase + 16 * 256 + aoff);
            const uint32_t bsz = ((ks * 2 + bchi) ^ bsw) << 4;
            #pragma unroll
            for (int gi = 0; gi < 2; gi++) {
                uint32_t b0, b1, b2, b3;
                ldsm_x4(b0, b1, b2, b3, Bb + gi * 4096 + bsz);
                mma16816(acc[0][2 * gi],     a0, a1, a2, a3, b0, b1);
                mma16816(acc[0][2 * gi + 1], a0, a1, a2, a3, b2, b3);
                mma16816(acc[1][2 * gi],     a4, a5, a6, a7, b0, b1);
                mma16816(acc[1][2 * gi + 1], a4, a5, a6, a7, b2, b3);
            }
        }

        int c0 = i * 64 + nh * 32;
        #pragma unroll
        for (int gi = 0; gi < 2; gi++) {
            #pragma unroll
            for (int h = 0; h < 2; h++) {
                int col = c0 + gi * 16 + h * 8 + t4 * 2;
                float2 en2 = *(const float2*)(en_s + col);
                #pragma unroll
                for (int mt = 0; mt < 2; mt++) {
                    float d0 = fmaf(-2.f, acc[mt][2 * gi + h][0], en2.x);
                    float d1 = fmaf(-2.f, acc[mt][2 * gi + h][1], en2.y);
                    float d2 = fmaf(-2.f, acc[mt][2 * gi + h][2], en2.x);
                    float d3 = fmaf(-2.f, acc[mt][2 * gi + h][3], en2.y);
                    upd3(q1[mt * 2][h],     qi[mt * 2][h],     q2[mt * 2][h],     d0, col);
                    upd3(q1[mt * 2][h],     qi[mt * 2][h],     q2[mt * 2][h],     d1, col + 1);
                    upd3(q1[mt * 2 + 1][h], qi[mt * 2 + 1][h], q2[mt * 2 + 1][h], d2, col);
                    upd3(q1[mt * 2 + 1][h], qi[mt * 2 + 1][h], q2[mt * 2 + 1][h], d3, col + 1);
                }
            }
        }
    }

    float fv1[4], fv2[4]; int fi1[4];
    #pragma unroll
    for (int s = 0; s < 4; s++) {
        fv1[s] = q1[s][0]; fv2[s] = q2[s][0]; fi1[s] = qi[s][0];
        merge3(fv1[s], fi1[s], fv2[s], q1[s][1], qi[s][1], q2[s][1]);
        #pragma unroll
        for (int m = 1; m <= 2; m <<= 1) {
            float ov1 = __shfl_xor_sync(0xffffffffu, fv1[s], m);
            int   oi1 = __shfl_xor_sync(0xffffffffu, fi1[s], m);
            float ov2 = __shfl_xor_sync(0xffffffffu, fv2[s], m);
            merge3(fv1[s], fi1[s], fv2[s], ov1, oi1, ov2);
        }
    }

    float* sv1 = (float*)(smem + SM_EN);
    float* sv2 = (float*)(smem + SM_EN + 1024);
    int*   si1 = (int*)(smem + SM_EN + 2048);
    __syncthreads();
    if (t4 == 0) {
        #pragma unroll
        for (int s = 0; s < 4; s++) {
            int rl = mq * 32 + (s >> 1) * 16 + (s & 1) * 8 + g;
            sv1[nh * 128 + rl] = fv1[s];
            sv2[nh * 128 + rl] = fv2[s];
            si1[nh * 128 + rl] = fi1[s];
        }
    }
    __syncthreads();
    if (tid < 128) {
        float v1 = sv1[tid], v2 = sv2[tid]; int i1 = si1[tid];
        merge3(v1, i1, v2, sv1[128 + tid], si1[128 + tid], sv2[128 + tid]);
        int row = row0 + tid;
        out[OFF_IND + row] = (float)i1;
        atomicAdd(&g_hist[i1], 1);
        if (v2 - v1 < MARGIN) {
            int p = atomicAdd(&g_fixn, 1);
            if (p < FIX_CAP) g_fixlist[p] = row;
        }
    }
}

// ---------------------------------------------------------------------------
// K1b: split-fp16 3-term mma rescue; item = (128-row tile, 1024-code quarter)
// + fused per-row 4-quarter merge & tier decision via completion counters
// ---------------------------------------------------------------------------
__global__ void __launch_bounds__(256, 1)
k_fixmma(const float* __restrict__ x, float* __restrict__ out) {
    extern __shared__ __align__(16) char smem[];
    const uint32_t sb = s2u(smem);
    const int tid  = threadIdx.x;
    const int warp = tid >> 5;
    const int lane = tid & 31;
    const int g    = lane >> 2;
    const int t4   = lane & 3;

    int nfix = g_fixn;
    if (nfix > FIX_CAP) nfix = FIX_CAP;
    if (nfix == 0) return;
    const int nrt = (nfix + 127) >> 7;
    const int nitems = nrt * 4;

    for (int u = tid; u < 1024; u += 256)
        CP_ASYNC16(sb + SM2_EN + u * 16, g_enorm + u * 4);
    CP_COMMIT();
    CP_WAIT(0);

    int* rowmap = (int*)(smem + SM2_ROWS);
    const float* en_s = (const float*)(smem + SM2_EN);

    const int bn   = (lane & 7) + ((lane >> 1) & 8);
    const int bchi = (lane >> 3) & 1;
    const int arow = warp * 16 + (lane & 15);
    const int achi = lane >> 4;
    const uint32_t ahbase = sb + SM2_AH + arow * 256;
    const uint32_t albase = sb + SM2_AL + arow * 256;
    const uint32_t boff   = (uint32_t)(bn * 256);
    const int bsw = bn & 7;
    const int asw = arow & 7;

    for (int item = blockIdx.x; item < nitems; item += gridDim.x) {
        const int tile = item >> 2;
        const int cq   = item & 3;
        __syncthreads();
        if (tid < 128) {
            int j = tile * 128 + tid;
            rowmap[tid] = g_fixlist[(j < nfix) ? j : (nfix - 1)];
        }
        __syncthreads();

        for (int u = tid; u < 2048; u += 256) {
            int r = u >> 4, s = u & 15;
            const float4* src = (const float4*)(x + (size_t)rowmap[r] * DIM + s * 8);
            float4 v0 = src[0], v1 = src[1];
            __half2 h0 = __floats2half2_rn(v0.x, v0.y);
            __half2 h1 = __floats2half2_rn(v0.z, v0.w);
            __half2 h2 = __floats2half2_rn(v1.x, v1.y);
            __half2 h3 = __floats2half2_rn(v1.z, v1.w);
            __half2 l0 = __floats2half2_rn(v0.x - __low2float(h0), v0.y - __high2float(h0));
            __half2 l1 = __floats2half2_rn(v0.z - __low2float(h1), v0.w - __high2float(h1));
            __half2 l2 = __floats2half2_rn(v1.x - __low2float(h2), v1.y - __high2float(h2));
            __half2 l3 = __floats2half2_rn(v1.z - __low2float(h3), v1.w - __high2float(h3));
            uint32_t sw = r * 256 + ((s ^ (r & 7)) << 4);
            *(uint4*)(smem + SM2_AH + sw) = make_uint4(*(uint32_t*)&h0, *(uint32_t*)&h1,
                                                       *(uint32_t*)&h2, *(uint32_t*)&h3);
            *(uint4*)(smem + SM2_AL + sw) = make_uint4(*(uint32_t*)&l0, *(uint32_t*)&l1,
                                                       *(uint32_t*)&l2, *(uint32_t*)&l3);
        }

        {
            const __half* eh = g_ehi + (size_t)(cq * 1024) * DIM;
            const __half* el = g_elo + (size_t)(cq * 1024) * DIM;
            uint32_t bb = sb + SM2_B;
            for (int u = tid; u < 1024; u += 256) {
                int n = u >> 4, s = u & 15;
                uint32_t sw = n * 256 + ((s ^ (n & 7)) << 4);
                CP_ASYNC16(bb + sw,         eh + n * DIM + s * 8);
                CP_ASYNC16(bb + 16384 + sw, el + n * DIM + s * 8);
            }
            CP_COMMIT();
        }

        float cav1[2], cav2[2], cbv1[2], cbv2[2];
        int   cai[2], cbi[2];
        #pragma unroll
        for (int k = 0; k < 2; k++) {
            cav1[k] = FLT_MAX; cav2[k] = FLT_MAX; cai[k] = 0;
            cbv1[k] = FLT_MAX; cbv2[k] = FLT_MAX; cbi[k] = 0;
        }

        for (int i = 0; i < 16; i++) {
            CP_WAIT(0);
            __syncthreads();
            if (i + 1 < 16) {
                const __half* eh = g_ehi + (size_t)((cq * 16 + i + 1) * 64) * DIM;
                const __half* el = g_elo + (size_t)((cq * 16 + i + 1) * 64) * DIM;
                uint32_t bb = sb + SM2_B + ((i + 1) & 1) * 32768;
                for (int u = tid; u < 1024; u += 256) {
                    int n = u >> 4, s = u & 15;
                    uint32_t sw = n * 256 + ((s ^ (n & 7)) << 4);
                    CP_ASYNC16(bb + sw,         eh + n * DIM + s * 8);
                    CP_ASYNC16(bb + 16384 + sw, el + n * DIM + s * 8);
                }
                CP_COMMIT();
            }

            const uint32_t Bh = sb + SM2_B + (i & 1) * 32768 + boff;
            const uint32_t Bl = Bh + 16384;

            float acc[8][4];
            #pragma unroll
            for (int nt = 0; nt < 8; nt++)
                #pragma unroll
                for (int j = 0; j < 4; j++) acc[nt][j] = 0.f;

            #pragma unroll
            for (int ks = 0; ks < 8; ks++) {
                uint32_t ah0, ah1, ah2, ah3, al0, al1, al2, al3;
                uint32_t aoff = ((ks * 2 + achi) ^ asw) << 4;
                ldsm_x4(ah0, ah1, ah2, ah3, ahbase + aoff);
                ldsm_x4(al0, al1, al2, al3, albase + aoff);
                const uint32_t bsz = ((ks * 2 + bchi) ^ bsw) << 4;
                #pragma unroll
                for (int gi = 0; gi < 4; gi++) {
                    uint32_t bh0, bh1, bh2, bh3, bl0, bl1, bl2, bl3;
                    ldsm_x4(bh0, bh1, bh2, bh3, Bh + gi * 4096 + bsz);
                    ldsm_x4(bl0, bl1, bl2, bl3, Bl + gi * 4096 + bsz);
                    mma16816(acc[2 * gi],     ah0, ah1, ah2, ah3, bh0, bh1);
                    mma16816(acc[2 * gi],     ah0, ah1, ah2, ah3, bl0, bl1);
                    mma16816(acc[2 * gi],     al0, al1, al2, al3, bh0, bh1);
                    mma16816(acc[2 * gi + 1], ah0, ah1, ah2, ah3, bh2, bh3);
                    mma16816(acc[2 * gi + 1], ah0, ah1, ah2, ah3, bl2, bl3);
                    mma16816(acc[2 * gi + 1], al0, al1, al2, al3, bh2, bh3);
                }
            }

            int c0 = (cq * 16 + i) * 64;
            #pragma unroll
            for (int nt = 0; nt < 8; nt++) {
                int ch  = nt & 1;
                int col = c0 + nt * 8 + t4 * 2;
                float2 en2 = *(const float2*)(en_s + col);
                float d0 = fmaf(-2.f, acc[nt][0], en2.x);
                float d1 = fmaf(-2.f, acc[nt][1], en2.y);
                float d2 = fmaf(-2.f, acc[nt][2], en2.x);
                float d3 = fmaf(-2.f, acc[nt][3], en2.y);
                upd3(cav1[ch], cai[ch], cav2[ch], d0, col);
                upd3(cav1[ch], cai[ch], cav2[ch], d1, col + 1);
                upd3(cbv1[ch], cbi[ch], cbv2[ch], d2, col);
                upd3(cbv1[ch], cbi[ch], cbv2[ch], d3, col + 1);
            }
        }

        float va1 = cav1[0], va2 = cav2[0]; int ia1 = cai[0];
        float vb1 = cbv1[0], vb2 = cbv2[0]; int ib1 = cbi[0];
        merge3(va1, ia1, va2, cav1[1], cai[1], cav2[1]);
        merge3(vb1, ib1, vb2, cbv1[1], cbi[1], cbv2[1]);
        #pragma unroll
        for (int m = 1; m <= 2; m <<= 1) {
            float ov1 = __shfl_xor_sync(0xffffffffu, va1, m);
            int   oi1 = __shfl_xor_sync(0xffffffffu, ia1, m);
            float ov2 = __shfl_xor_sync(0xffffffffu, va2, m);
            merge3(va1, ia1, va2, ov1, oi1, ov2);
            ov1 = __shfl_xor_sync(0xffffffffu, vb1, m);
            oi1 = __shfl_xor_sync(0xffffffffu, ib1, m);
            ov2 = __shfl_xor_sync(0xffffffffu, vb2, m);
            merge3(vb1, ib1, vb2, ov1, oi1, ov2);
        }

        if (t4 == 0) {
            int rlA = warp * 16 + g;
            int rlB = rlA + 8;
            int jA = tile * 128 + rlA;
            int jB = tile * 128 + rlB;
            #pragma unroll
            for (int half = 0; half < 2; half++) {
                int j = half ? jB : jA;
                if (j >= nfix) continue;
                float w1 = half ? vb1 : va1;
                float w2 = half ? vb2 : va2;
                int   wi = half ? ib1 : ia1;
                g_qv1[j * 4 + cq] = w1;
                g_qv2[j * 4 + cq] = w2;
                g_qi1[j * 4 + cq] = wi;
                __threadfence();
                int old = atomicAdd(&g_qcnt[j], 1);
                if (old == 3) {
                    // all 4 quarters done: merge + tier decision
                    float b1 = g_qv1[j * 4], b2 = g_qv2[j * 4]; int bi = g_qi1[j * 4];
                    #pragma unroll
                    for (int c = 1; c < 4; c++)
                        merge3(b1, bi, b2, g_qv1[j * 4 + c], g_qi1[j * 4 + c], g_qv2[j * 4 + c]);
                    int row = g_fixlist[j];
                    if (b2 - b1 < MARGIN2) {
                        int p = atomicAdd(&g_fixn2, 1);
                        if (p < FIX2_CAP) g_fixlist2[p] = row;
                    } else {
                        int oldi = (int)out[OFF_IND + row];
                        if (oldi != bi) {
                            out[OFF_IND + row] = (float)bi;
                            atomicAdd(&g_hist[oldi], -1);
                            atomicAdd(&g_hist[bi], 1);
                        }
                    }
                }
            }
        }
    }
}

// ---------------------------------------------------------------------------
// K1d: exact fp32 partial rescan over SECOND-level list (tiny)
// + fused 8-way merge via per-rowgroup completion counters
// ---------------------------------------------------------------------------
__global__ void __launch_bounds__(256)
k_fixpart(const float* __restrict__ x, float* __restrict__ out) {
    __shared__ float xs[16 * 132];
    __shared__ float cs[2][32 * 132];
    __shared__ float rbv[16 * 8];
    __shared__ int   rbi[16 * 8];
    __shared__ int   rowids[16];
    __shared__ int   s_winner;
    const uint32_t cs0 = s2u(&cs[0][0]);
    const uint32_t cs1 = s2u(&cs[1][0]);

    int nfix = g_fixn2;
    if (nfix > FIX2_CAP) nfix = FIX2_CAP;
    if (nfix == 0) return;
    const int nrg = (nfix + 15) >> 4;
    const int nitems = nrg * 8;

    const int tid  = threadIdx.x;
    const int ds   = tid & 3;
    const int tile = tid >> 2;
    const int tr   = tile >> 3;
    const int tc   = tile & 7;

    for (int item = blockIdx.x; item < nitems; item += gridDim.x) {
        const int rg = item >> 3;
        const int cg = item & 7;
        const int base = rg * 16;
        const int nr = (nfix - base < 16) ? (nfix - base) : 16;

        if (tid < 16) {
            int j = base + tid;
            rowids[tid] = g_fixlist2[(j < nfix) ? j : (nfix - 1)];
        }
        __syncthreads();
        for (int u = tid; u < 512; u += 256) {
            int r = u >> 5, q = u & 31;
            float4 v = ((const float4*)(x + (size_t)rowids[r] * DIM))[q];
            *(float4*)(xs + r * 132 + q * 4) = v;
        }
        {
            const float* src = g_embedT + (size_t)(cg * 512) * DIM;
            for (int u = tid; u < 1024; u += 256) {
                int c = u >> 5, q = u & 31;
                CP_ASYNC16(cs0 + (uint32_t)(c * 528 + q * 16), src + (size_t)c * DIM + q * 4);
            }
            CP_COMMIT();
        }

        float bv[2]; int bi[2];
        bv[0] = bv[1] = FLT_MAX; bi[0] = bi[1] = 0;

        for (int ci = 0; ci < 16; ci++) {
            CP_WAIT(0);
            __syncthreads();
            if (ci + 1 < 16) {
                uint32_t dst = ((ci + 1) & 1) ? cs1 : cs0;
                const float* src = g_embedT + (size_t)(cg * 512 + (ci + 1) * 32) * DIM;
                for (int u = tid; u < 1024; u += 256) {
                    int c = u >> 5, q = u & 31;
                    CP_ASYNC16(dst + (uint32_t)(c * 528 + q * 16), src + (size_t)c * DIM + q * 4);
                }
                CP_COMMIT();
            }
            const float* csb = cs[ci & 1];

            float acc[2][4];
            #pragma unroll
            for (int rr = 0; rr < 2; rr++)
                #pragma unroll
                for (int cc = 0; cc < 4; cc++) acc[rr][cc] = 0.f;

            #pragma unroll
            for (int d4 = 0; d4 < 8; d4++) {
                int d = ds * 32 + d4 * 4;
                float4 cv[4], rv[2];
                #pragma unroll
                for (int cc = 0; cc < 4; cc++) cv[cc] = *(const float4*)(csb + (tc * 4 + cc) * 132 + d);
                #pragma unroll
                for (int rr = 0; rr < 2; rr++) rv[rr] = *(const float4*)(xs + (tr * 2 + rr) * 132 + d);
                #pragma unroll
                for (int rr = 0; rr < 2; rr++)
                    #pragma unroll
                    for (int cc = 0; cc < 4; cc++)
                        acc[rr][cc] += rv[rr].x * cv[cc].x + rv[rr].y * cv[cc].y +
                                       rv[rr].z * cv[cc].z + rv[rr].w * cv[cc].w;
            }
            #pragma unroll
            for (int rr = 0; rr < 2; rr++)
                #pragma unroll
                for (int cc = 0; cc < 4; cc++) {
                    float a = acc[rr][cc];
                    a += __shfl_xor_sync(0xffffffffu, a, 1);
                    a += __shfl_xor_sync(0xffffffffu, a, 2);
                    acc[rr][cc] = a;
                }
            #pragma unroll
            for (int cc = 0; cc < 4; cc++) {
                int code = cg * 512 + ci * 32 + tc * 4 + cc;
                float en = __ldg(g_enorm + code);
                #pragma unroll
                for (int rr = 0; rr < 2; rr++) {
                    float dv = fmaf(-2.f, acc[rr][cc], en);
                    if (dv < bv[rr]) { bv[rr] = dv; bi[rr] = code; }
                }
            }
        }
        __syncthreads();
        if (ds == 0) {
            #pragma unroll
            for (int rr = 0; rr < 2; rr++) {
                rbv[(tr * 2 + rr) * 8 + tc] = bv[rr];
                rbi[(tr * 2 + rr) * 8 + tc] = bi[rr];
            }
        }
        __syncthreads();
        if (tid < nr) {
            float b = rbv[tid * 8]; int bidx = rbi[tid * 8];
            #pragma unroll
            for (int jj = 1; jj < 8; jj++) {
                float v = rbv[tid * 8 + jj]; int idx = rbi[tid * 8 + jj];
                if (v < b || (v == b && idx < bidx)) { b = v; bidx = idx; }
            }
            g_pv[(base + tid) * 8 + cg] = b;
            g_pi[(base + tid) * 8 + cg] = bidx;
        }
        __syncthreads();
        __threadfence();
        if (tid == 0) {
            int old = atomicAdd(&g_cnt2[rg], 1);
            s_winner = (old == 7) ? 1 : 0;
        }
        __syncthreads();
        if (s_winner && tid < nr) {
            int j = base + tid;
            float b = g_pv[j * 8]; int bidx = g_pi[j * 8];
            #pragma unroll
            for (int c = 1; c < 8; c++) {
                float v = g_pv[j * 8 + c]; int idx = g_pi[j * 8 + c];
                if (v < b || (v == b && idx < bidx)) { b = v; bidx = idx; }
            }
            int row = g_fixlist2[j];
            int old = (int)out[OFF_IND + row];
            if (old != bidx) {
                out[OFF_IND + row] = (float)bidx;
                atomicAdd(&g_hist[old], -1);
                atomicAdd(&g_hist[bidx], 1);
            }
        }
        __syncthreads();
    }
}

// ---------------------------------------------------------------------------
// K2: prefix sum over hist -> offsets; cluster_size_new; n; n_small
// ---------------------------------------------------------------------------
__global__ void k_prefix(float* __restrict__ out) {
    __shared__ int   wsum[32];
    __shared__ float fsum[32];
    __shared__ int   fcnt[32];
    int t = threadIdx.x;
    int h0 = g_hist[t * 4], h1 = g_hist[t * 4 + 1], h2 = g_hist[t * 4 + 2], h3 = g_hist[t * 4 + 3];
    int loc = h0 + h1 + h2 + h3;
    int pre = loc;
    #pragma unroll
    for (int o = 1; o < 32; o <<= 1) {
        int n = __shfl_up_sync(0xffffffffu, pre, o);
        if ((t & 31) >= o) pre += n;
    }
    if ((t & 31) == 31) wsum[t >> 5] = pre;
    __syncthreads();
    if (t < 32) {
        int v = wsum[t];
        #pragma unroll
        for (int o = 1; o < 32; o <<= 1) {
            int n = __shfl_up_sync(0xffffffffu, v, o);
            if (t >= o) v += n;
        }
        wsum[t] = v;
    }
    __syncthreads();
    int base = pre - loc + ((t >= 32) ? wsum[(t >> 5) - 1] : 0);
    g_off[t * 4]     = base;
    g_off[t * 4 + 1] = base + h0;
    g_off[t * 4 + 2] = base + h0 + h1;
    g_off[t * 4 + 3] = base + h0 + h1 + h2;
    float c0 = out[OFF_CS + t * 4]     + ONE_M_D * (float)h0;
    float c1 = out[OFF_CS + t * 4 + 1] + ONE_M_D * (float)h1;
    float c2 = out[OFF_CS + t * 4 + 2] + ONE_M_D * (float)h2;
    float c3 = out[OFF_CS + t * 4 + 3] + ONE_M_D * (float)h3;
    out[OFF_CS + t * 4]     = c0;
    out[OFF_CS + t * 4 + 1] = c1;
    out[OFF_CS + t * 4 + 2] = c2;
    out[OFF_CS + t * 4 + 3] = c3;
    float s = c0 + c1 + c2 + c3;
    int   c = (c0 < 1.f) + (c1 < 1.f) + (c2 < 1.f) + (c3 < 1.f);
    #pragma unroll
    for (int o = 16; o > 0; o >>= 1) {
        s += __shfl_down_sync(0xffffffffu, s, o);
        c += __shfl_down_sync(0xffffffffu, c, o);
    }
    if ((t & 31) == 0) { fsum[t >> 5] = s; fcnt[t >> 5] = c; }
    __syncthreads();
    if (t < 32) {
        s = fsum[t]; c = fcnt[t];
        #pragma unroll
        for (int o = 16; o > 0; o >>= 1) {
            s += __shfl_down_sync(0xffffffffu, s, o);
            c += __shfl_down_sync(0xffffffffu, c, o);
        }
        if (t == 0) { g_n = s; out[OFF_NSMALL] = (float)c; }
    }
}

// ---------------------------------------------------------------------------
// K2c: bin rows by code (barrier-free)
// ---------------------------------------------------------------------------
__global__ void k_scatter(const float* __restrict__ out_c) {
    int i = blockIdx.x * 256 + threadIdx.x;
    if (i >= N_ROWS) return;
    int idx = (int)out_c[OFF_IND + i];
    int pos = atomicAdd(&g_cur[idx], 1);
    g_rowlist[g_off[idx] + pos] = i;
}

// ---------------------------------------------------------------------------
// K2d: per-code gather-sum into embed_avg_new (one warp per code)
// ---------------------------------------------------------------------------
__global__ void __launch_bounds__(256)
k_avg(const float* __restrict__ x, float* __restrict__ out) {
    int c    = blockIdx.x * 8 + (threadIdx.x >> 5);
    int lane = threadIdx.x & 31;
    int cnt  = g_hist[c];
    int base = g_off[c];
    float4 s = make_float4(0.f, 0.f, 0.f, 0.f);
    for (int j = 0; j < cnt; j++) {
        int r = g_rowlist[base + j];
        float4 v = ((const float4*)(x + (size_t)r * DIM))[lane];
        s.x += v.x; s.y += v.y; s.z += v.z; s.w += v.w;
    }
    if (cnt > 0) {
        out[OFF_EAVG + (size_t)(lane * 4 + 0) * K_CODES + c] += ONE_M_D * s.x;
        out[OFF_EAVG + (size_t)(lane * 4 + 1) * K_CODES + c] += ONE_M_D * s.y;
        out[OFF_EAVG + (size_t)(lane * 4 + 2) * K_CODES + c] += ONE_M_D * s.z;
        out[OFF_EAVG + (size_t)(lane * 4 + 3) * K_CODES + c] += ONE_M_D * s.w;
    }
}

// ---------------------------------------------------------------------------
// K3: quantize gather + loss (all rows, final indices; spread atomic slots)
// ---------------------------------------------------------------------------
__global__ void __launch_bounds__(256)
k_post(const float* __restrict__ x, float* __restrict__ out) {
    __shared__ float wls[8];
    int warp = threadIdx.x >> 5;
    int lane = threadIdx.x & 31;
    int row  = blockIdx.x * 8 + warp;
    int idx  = (int)out[OFF_IND + row];
    float4 q  = ((const float4*)(g_embedT + (size_t)idx * DIM))[lane];
    float4 xv = ((const float4*)(x + (size_t)row * DIM))[lane];
    ((float4*)(out + OFF_Q + (size_t)row * DIM))[lane] = q;
    float d0 = q.x - xv.x, d1 = q.y - xv.y, d2 = q.z - xv.z, d3 = q.w - xv.w;
    float lsum = d0 * d0 + d1 * d1 + d2 * d2 + d3 * d3;
    #pragma unroll
    for (int o = 16; o > 0; o >>= 1) lsum += __shfl_down_sync(0xffffffffu, lsum, o);
    if (lane == 0) wls[warp] = lsum;
    __syncthreads();
    if (threadIdx.x == 0) {
        float b = wls[0] + wls[1] + wls[2] + wls[3] + wls[4] + wls[5] + wls[6] + wls[7];
        atomicAdd(&g_losspart[blockIdx.x & 127], (double)b);
    }
}

// ---------------------------------------------------------------------------
// K5: embed_new = embed_avg_new / cs_norm; finalize loss
// ---------------------------------------------------------------------------
__global__ void k_final(float* __restrict__ out) {
    int i = blockIdx.x * 256 + threadIdx.x;
    if (i < DIM * K_CODES) {
        int k = i & (K_CODES - 1);
        float n   = g_n;
        float cs  = out[OFF_CS + k];
        float csn = (cs + EPS) / (n + (float)K_CODES * EPS) * n;
        out[OFF_ENEW + i] = out[OFF_EAVG + i] / csn;
    }
    if (blockIdx.x == 0 && threadIdx.x == 0) {
        double tot = 0.0;
        #pragma unroll
        for (int j = 0; j < 128; j++) tot += g_losspart[j];
        out[OFF_LOSS] = (float)(tot / ((double)N_ROWS * (double)DIM));
    }
}

// ---------------------------------------------------------------------------
extern "C" void kernel_launch(void* const* d_in, const int* in_sizes, int n_in,
                              void* d_out, int out_size) {
    const float* x            = (const float*)d_in[0];
    const float* embed        = (const float*)d_in[1];
    const float* cluster_size = (const float*)d_in[2];
    const float* embed_avg    = (const float*)d_in[3];
    float* out = (float*)d_out;

    cudaFuncSetAttribute(k_mma, cudaFuncAttributeMaxDynamicSharedMemorySize, SMEM_MMA_BYTES);
    cudaFuncSetAttribute(k_fixmma, cudaFuncAttributeMaxDynamicSharedMemorySize, SMEM_FIXMMA_BYTES);

    k_init<<<(DIM * K_CODES + 255) / 256, 256>>>(cluster_size, embed_avg, out);
    k_prepe<<<dim3(K_CODES / 32, DIM / 32), dim3(32, 8)>>>(embed);
    k_mma<<<N_ROWS / 128, 256, SMEM_MMA_BYTES>>>(x, out);
    k_fixmma<<<512, 256, SMEM_FIXMMA_BYTES>>>(x, out);
    k_fixpart<<<256, 256>>>(x, out);
    k_prefix<<<1, 1024>>>(out);
    k_scatter<<<N_ROWS / 256, 256>>>(out);
    k_avg<<<K_CODES / 8, 256>>>(x, out);
    k_post<<<N_ROWS / 8, 256>>>(x, out);
    k_final<<<(DIM * K_CODES + 255) / 256, 256>>>(out);
}